// round 2
// baseline (speedup 1.0000x reference)
#include <cuda_runtime.h>
#include <math.h>

typedef unsigned long long ull;

#define NB 128
#define ND 256
#define NH 1024
#define NT 512
#define NH3 3072
#define NBLK 128
#define NTHR 256

// ---------------- scratch (static device globals; no runtime allocation) ----
__device__ float g_P[(size_t)NT * NB * NH3];   // x-projections (+bias), [b*T+t][3H]
__device__ float g_gamma[NT * NH];             // decay per (t, j)
__device__ float g_a[NB * NH];                 // a = gamma_t * h_{t-1}
__device__ float g_z[NB * NH];                 // z gate
__device__ float g_r[NB * NH];                 // r gate
__device__ float g_zrpart[8][NB * 2 * NH];     // split-K partials for z,r GEMM
__device__ float g_hpart[16][NB * NH];         // split-K partials for h~ GEMM

// ---------------- grid barrier ----------------------------------------------
__device__ unsigned g_bar_count = 0;
__device__ volatile unsigned g_bar_gen = 0;

__device__ __forceinline__ void gridbar() {
    __syncthreads();
    if (threadIdx.x == 0) {
        unsigned gen = g_bar_gen;
        __threadfence();
        if (atomicAdd(&g_bar_count, 1) == NBLK - 1) {
            g_bar_count = 0;
            __threadfence();
            g_bar_gen = gen + 1;
        } else {
            while (g_bar_gen == gen) { __nanosleep(64); }
            __threadfence();
        }
    }
    __syncthreads();
}

// ---------------- packed fp32x2 helpers -------------------------------------
__device__ __forceinline__ void ffma2(ull& c, ull a, ull b) {
    asm("fma.rn.f32x2 %0, %1, %2, %3;" : "=l"(c) : "l"(a), "l"(b), "l"(c));
}
__device__ __forceinline__ ull pack2(float x, float y) {
    ull r; asm("mov.b64 %0, {%1, %2};" : "=l"(r) : "f"(x), "f"(y)); return r;
}
__device__ __forceinline__ float2 unpack2(ull v) {
    float2 r; asm("mov.b64 {%0, %1}, %2;" : "=f"(r.x), "=f"(r.y) : "l"(v)); return r;
}
__device__ __forceinline__ float sigmf(float x) { return 1.f / (1.f + expf(-x)); }

// ---------------- x-projection GEMM: P = X @ [Wxz|Wxr|Wxh] + bias -----------
__global__ __launch_bounds__(256) void k_xproj(
    const float* __restrict__ value,
    const float* __restrict__ wxz, const float* __restrict__ wxr,
    const float* __restrict__ wxh,
    const float* __restrict__ bbz, const float* __restrict__ bbr,
    const float* __restrict__ bbh)
{
    __shared__ float As[8][132];
    __shared__ float Bs[8][128];
    const int n0 = blockIdx.x * 128;
    const int m0 = blockIdx.y * 128;
    const int gate = n0 >> 10;
    const int j0 = n0 & (NH - 1);
    const float* W    = (gate == 0) ? wxz : (gate == 1 ? wxr : wxh);
    const float* bias = (gate == 0) ? bbz : (gate == 1 ? bbr : bbh);
    const int b  = m0 >> 9;           // T = 512
    const int t0 = m0 & (NT - 1);
    const int tid = threadIdx.x;
    const int tx = tid & 15, ty = tid >> 4;

    ull acc[8][4];
#pragma unroll
    for (int r = 0; r < 8; r++)
#pragma unroll
        for (int c = 0; c < 4; c++) acc[r][c] = 0ull;

    const float* Abase = value + (size_t)b * ND * NT + t0;  // A[m,k] = value[(b*D+k)*T + t]

    for (int kc = 0; kc < ND; kc += 8) {
#pragma unroll
        for (int i = 0; i < 4; i++) {
            int idx = i * 256 + tid; int mm = idx & 127; int kk = idx >> 7;
            As[kk][mm] = Abase[(size_t)(kc + kk) * NT + mm];
        }
#pragma unroll
        for (int i = 0; i < 4; i++) {
            int idx = i * 256 + tid; int nn = idx & 127; int kk = idx >> 7;
            Bs[kk][nn] = W[(size_t)(kc + kk) * NH + j0 + nn];
        }
        __syncthreads();
#pragma unroll
        for (int k = 0; k < 8; k++) {
            float4 a0 = *(const float4*)&As[k][ty * 8];
            float4 a1 = *(const float4*)&As[k][ty * 8 + 4];
            ull b0 = *(const ull*)&Bs[k][tx * 8];
            ull b1 = *(const ull*)&Bs[k][tx * 8 + 2];
            ull b2 = *(const ull*)&Bs[k][tx * 8 + 4];
            ull b3 = *(const ull*)&Bs[k][tx * 8 + 6];
            float av[8] = {a0.x, a0.y, a0.z, a0.w, a1.x, a1.y, a1.z, a1.w};
#pragma unroll
            for (int r = 0; r < 8; r++) {
                ull aa = pack2(av[r], av[r]);
                ffma2(acc[r][0], aa, b0);
                ffma2(acc[r][1], aa, b1);
                ffma2(acc[r][2], aa, b2);
                ffma2(acc[r][3], aa, b3);
            }
        }
        __syncthreads();
    }
#pragma unroll
    for (int r = 0; r < 8; r++) {
        int m = m0 + ty * 8 + r;
        float* dst = g_P + (size_t)m * NH3 + n0 + tx * 8;
        const float* bp = bias + j0 + tx * 8;
        float o[8];
#pragma unroll
        for (int c = 0; c < 4; c++) {
            float2 v = unpack2(acc[r][c]);
            o[2 * c]     = v.x + bp[2 * c];
            o[2 * c + 1] = v.y + bp[2 * c + 1];
        }
        *(float4*)dst       = make_float4(o[0], o[1], o[2], o[3]);
        *(float4*)(dst + 4) = make_float4(o[4], o[5], o[6], o[7]);
    }
}

// ---------------- persistent recurrence kernel ------------------------------
__global__ __launch_bounds__(NTHR, 1) void k_persist(
    const float* __restrict__ delta,
    const float* __restrict__ wdg, const float* __restrict__ bdg,
    const float* __restrict__ whz, const float* __restrict__ whr,
    const float* __restrict__ whh,
    float* __restrict__ out, float* __restrict__ hlast)
{
    __shared__ float As[8][132];
    __shared__ float Bs[8][128];
    const int bid = blockIdx.x;
    const int tid = threadIdx.x;
    const int tx = tid & 15, ty = tid >> 4;

    // ---- prologue: gamma + zero a ----
    {
        // gamma: NT*NH = 524288 elems; 4096 per block, 4 per thread per iter
        for (int it = 0; it < 4; it++) {
            int idx4 = bid * 1024 + it * 256 + tid;   // float4 index
            int i = idx4 * 4;
            int t = i >> 10, j = i & (NH - 1);
            float d = delta[t];
            float4 w = *(const float4*)(wdg + j);
            float4 bb = *(const float4*)(bdg + j);
            float4 g;
            g.x = expf(-fmaxf(0.f, w.x * d + bb.x));
            g.y = expf(-fmaxf(0.f, w.y * d + bb.y));
            g.z = expf(-fmaxf(0.f, w.z * d + bb.z));
            g.w = expf(-fmaxf(0.f, w.w * d + bb.w));
            *(float4*)(g_gamma + i) = g;
        }
        *(float4*)(g_a + bid * NH + tid * 4) = make_float4(0.f, 0.f, 0.f, 0.f);
    }
    gridbar();

    for (int t = 0; t < NT; t++) {
        // ---- Phase A: zr partial GEMM: g_a @ [Whz|Whr], split-K=8 ----
        {
            const int n0 = (bid >> 3) * 128;         // 0..2047
            const int ks = bid & 7;
            const int kbase = ks * 128;
            const int gate = n0 >> 10;
            const int j0 = n0 & (NH - 1);
            const float* W = gate ? whr : whz;

            ull acc[8][4];
#pragma unroll
            for (int r = 0; r < 8; r++)
#pragma unroll
                for (int c = 0; c < 4; c++) acc[r][c] = 0ull;

            for (int kc = 0; kc < 128; kc += 8) {
                int kg0 = kbase + kc;
#pragma unroll
                for (int i = 0; i < 4; i++) {
                    int idx = i * 256 + tid; int kk = idx & 7; int mm = idx >> 3;
                    As[kk][mm] = g_a[mm * NH + kg0 + kk];
                }
#pragma unroll
                for (int i = 0; i < 4; i++) {
                    int idx = i * 256 + tid; int nn = idx & 127; int kk = idx >> 7;
                    Bs[kk][nn] = W[(size_t)(kg0 + kk) * NH + j0 + nn];
                }
                __syncthreads();
#pragma unroll
                for (int k = 0; k < 8; k++) {
                    float4 a0 = *(const float4*)&As[k][ty * 8];
                    float4 a1 = *(const float4*)&As[k][ty * 8 + 4];
                    ull b0 = *(const ull*)&Bs[k][tx * 8];
                    ull b1 = *(const ull*)&Bs[k][tx * 8 + 2];
                    ull b2 = *(const ull*)&Bs[k][tx * 8 + 4];
                    ull b3 = *(const ull*)&Bs[k][tx * 8 + 6];
                    float av[8] = {a0.x, a0.y, a0.z, a0.w, a1.x, a1.y, a1.z, a1.w};
#pragma unroll
                    for (int r = 0; r < 8; r++) {
                        ull aa = pack2(av[r], av[r]);
                        ffma2(acc[r][0], aa, b0);
                        ffma2(acc[r][1], aa, b1);
                        ffma2(acc[r][2], aa, b2);
                        ffma2(acc[r][3], aa, b3);
                    }
                }
                __syncthreads();
            }
            float* part = g_zrpart[ks];
#pragma unroll
            for (int r = 0; r < 8; r++) {
                int m = ty * 8 + r;
                float* dst = part + m * 2 * NH + n0 + tx * 8;
                float2 v0 = unpack2(acc[r][0]);
                float2 v1 = unpack2(acc[r][1]);
                float2 v2 = unpack2(acc[r][2]);
                float2 v3 = unpack2(acc[r][3]);
                *(float4*)dst       = make_float4(v0.x, v0.y, v1.x, v1.y);
                *(float4*)(dst + 4) = make_float4(v2.x, v2.y, v3.x, v3.y);
            }
        }
        gridbar();

        // ---- Phase B: z, r gates (block bid handles batch row b = bid) ----
        {
            const int b = bid;
            const float4* Pp = (const float4*)(g_P + ((size_t)(b * NT + t)) * NH3);
            float4 sz = Pp[tid];
            float4 sr = Pp[256 + tid];
#pragma unroll
            for (int ks = 0; ks < 8; ks++) {
                const float4* zp = (const float4*)(g_zrpart[ks] + b * 2 * NH);
                float4 v = zp[tid];
                sz.x += v.x; sz.y += v.y; sz.z += v.z; sz.w += v.w;
                float4 w = zp[256 + tid];
                sr.x += w.x; sr.y += w.y; sr.z += w.z; sr.w += w.w;
            }
            float4 zz = make_float4(sigmf(sz.x), sigmf(sz.y), sigmf(sz.z), sigmf(sz.w));
            float4 rr = make_float4(sigmf(sr.x), sigmf(sr.y), sigmf(sr.z), sigmf(sr.w));
            *(float4*)(g_z + b * NH + tid * 4) = zz;
            *(float4*)(g_r + b * NH + tid * 4) = rr;
        }
        gridbar();

        // ---- Phase C: h~ partial GEMM: (r*a) @ Whh, split-K=16 ----
        {
            const int n0 = (bid >> 4) * 128;         // 0..1023
            const int ks = bid & 15;
            const int kbase = ks * 64;

            ull acc[8][4];
#pragma unroll
            for (int r = 0; r < 8; r++)
#pragma unroll
                for (int c = 0; c < 4; c++) acc[r][c] = 0ull;

            for (int kc = 0; kc < 64; kc += 8) {
                int kg0 = kbase + kc;
#pragma unroll
                for (int i = 0; i < 4; i++) {
                    int idx = i * 256 + tid; int kk = idx & 7; int mm = idx >> 3;
                    int kg = kg0 + kk;
                    As[kk][mm] = g_r[mm * NH + kg] * g_a[mm * NH + kg];
                }
#pragma unroll
                for (int i = 0; i < 4; i++) {
                    int idx = i * 256 + tid; int nn = idx & 127; int kk = idx >> 7;
                    Bs[kk][nn] = whh[(size_t)(kg0 + kk) * NH + n0 + nn];
                }
                __syncthreads();
#pragma unroll
                for (int k = 0; k < 8; k++) {
                    float4 a0 = *(const float4*)&As[k][ty * 8];
                    float4 a1 = *(const float4*)&As[k][ty * 8 + 4];
                    ull b0 = *(const ull*)&Bs[k][tx * 8];
                    ull b1 = *(const ull*)&Bs[k][tx * 8 + 2];
                    ull b2 = *(const ull*)&Bs[k][tx * 8 + 4];
                    ull b3 = *(const ull*)&Bs[k][tx * 8 + 6];
                    float av[8] = {a0.x, a0.y, a0.z, a0.w, a1.x, a1.y, a1.z, a1.w};
#pragma unroll
                    for (int r = 0; r < 8; r++) {
                        ull aa = pack2(av[r], av[r]);
                        ffma2(acc[r][0], aa, b0);
                        ffma2(acc[r][1], aa, b1);
                        ffma2(acc[r][2], aa, b2);
                        ffma2(acc[r][3], aa, b3);
                    }
                }
                __syncthreads();
            }
            float* part = g_hpart[ks];
#pragma unroll
            for (int r = 0; r < 8; r++) {
                int m = ty * 8 + r;
                float* dst = part + m * NH + n0 + tx * 8;
                float2 v0 = unpack2(acc[r][0]);
                float2 v1 = unpack2(acc[r][1]);
                float2 v2 = unpack2(acc[r][2]);
                float2 v3 = unpack2(acc[r][3]);
                *(float4*)dst       = make_float4(v0.x, v0.y, v1.x, v1.y);
                *(float4*)(dst + 4) = make_float4(v2.x, v2.y, v3.x, v3.y);
            }
        }
        gridbar();

        // ---- Phase D: h update, output, next a ----
        {
            const int b = bid;
            const float4* Pp = (const float4*)(g_P + ((size_t)(b * NT + t)) * NH3);
            float4 sh = Pp[512 + tid];
#pragma unroll
            for (int ks = 0; ks < 16; ks++) {
                const float4* hp = (const float4*)(g_hpart[ks] + b * NH);
                float4 v = hp[tid];
                sh.x += v.x; sh.y += v.y; sh.z += v.z; sh.w += v.w;
            }
            float4 zz = *(const float4*)(g_z + b * NH + tid * 4);
            float4 aa = *(const float4*)(g_a + b * NH + tid * 4);
            float4 hn;
            hn.x = (1.f - zz.x) * aa.x + zz.x * tanhf(sh.x);
            hn.y = (1.f - zz.y) * aa.y + zz.y * tanhf(sh.y);
            hn.z = (1.f - zz.z) * aa.z + zz.z * tanhf(sh.z);
            hn.w = (1.f - zz.w) * aa.w + zz.w * tanhf(sh.w);
            *(float4*)(out + ((size_t)(b * NT + t)) * NH + tid * 4) = hn;
            if (t + 1 < NT) {
                float4 gn = *(const float4*)(g_gamma + (t + 1) * NH + tid * 4);
                float4 an;
                an.x = gn.x * hn.x; an.y = gn.y * hn.y;
                an.z = gn.z * hn.z; an.w = gn.w * hn.w;
                *(float4*)(g_a + b * NH + tid * 4) = an;
            } else {
                *(float4*)(hlast + b * NH + tid * 4) = hn;
            }
        }
        gridbar();
    }
}

// ---------------- launch -----------------------------------------------------
extern "C" void kernel_launch(void* const* d_in, const int* in_sizes, int n_in,
                              void* d_out, int out_size) {
    const float* value = (const float*)d_in[0];
    const float* delta = (const float*)d_in[1];
    const float* wdg   = (const float*)d_in[2];
    const float* wxz   = (const float*)d_in[3];
    const float* whz   = (const float*)d_in[4];
    const float* wxr   = (const float*)d_in[5];
    const float* whr   = (const float*)d_in[6];
    const float* wxh   = (const float*)d_in[7];
    const float* whh   = (const float*)d_in[8];
    const float* bz    = (const float*)d_in[10];
    const float* br    = (const float*)d_in[11];
    const float* bh    = (const float*)d_in[12];
    const float* bdg   = (const float*)d_in[9];
    float* out = (float*)d_out;
    float* hlast = out + ((size_t)out_size - (size_t)NB * NH);

    k_xproj<<<dim3(24, 512), 256>>>(value, wxz, wxr, wxh, bz, br, bh);
    k_persist<<<NBLK, NTHR>>>(delta, wdg, bdg, whz, whr, whh, out, hlast);
}

// round 4
// speedup vs baseline: 1.6655x; 1.6655x over previous
#include <cuda_runtime.h>
#include <cuda_bf16.h>
#include <math.h>
#include <stdint.h>

typedef unsigned long long ull;

#define NB 128
#define ND 256
#define NH 1024
#define NT 512
#define NH3 3072
#define NBLK 128
#define NTHR 256

// ---------------- scratch (static device globals) ---------------------------
__device__ float g_P[(size_t)NT * NB * NH3];   // x-projections (+bias)
__device__ float g_gamma[NT * NH];
__device__ float g_a[NB * NH];                 // a = gamma_t * h_{t-1}
__device__ float g_z[NB * NH];
__device__ float g_r[NB * NH];
__device__ float g_zrpart[8][NB * 2 * NH];
__device__ float g_hpart[16][NB * NH];

// ---------------- grid barrier ----------------------------------------------
__device__ unsigned g_bar_count = 0;
__device__ volatile unsigned g_bar_gen = 0;

__device__ __forceinline__ void gridbar() {
    __syncthreads();
    if (threadIdx.x == 0) {
        unsigned gen = g_bar_gen;
        __threadfence();
        if (atomicAdd(&g_bar_count, 1) == NBLK - 1) {
            g_bar_count = 0;
            __threadfence();
            g_bar_gen = gen + 1;
        } else {
            while (g_bar_gen == gen) { __nanosleep(32); }
            __threadfence();
        }
    }
    __syncthreads();
}

// ---------------- helpers ----------------------------------------------------
__device__ __forceinline__ float sigmf(float x) { return 1.f / (1.f + expf(-x)); }

__device__ __forceinline__ uint32_t pack_bf2(__nv_bfloat16 a, __nv_bfloat16 b) {
    return ((uint32_t)__bfloat16_as_ushort(b) << 16) | (uint32_t)__bfloat16_as_ushort(a);
}
__device__ __forceinline__ void split4(float x0, float x1, float x2, float x3,
                                       uint2& hi, uint2& lo) {
    __nv_bfloat16 h0 = __float2bfloat16_rn(x0), h1 = __float2bfloat16_rn(x1);
    __nv_bfloat16 h2 = __float2bfloat16_rn(x2), h3 = __float2bfloat16_rn(x3);
    __nv_bfloat16 l0 = __float2bfloat16_rn(x0 - __bfloat162float(h0));
    __nv_bfloat16 l1 = __float2bfloat16_rn(x1 - __bfloat162float(h1));
    __nv_bfloat16 l2 = __float2bfloat16_rn(x2 - __bfloat162float(h2));
    __nv_bfloat16 l3 = __float2bfloat16_rn(x3 - __bfloat162float(h3));
    hi = make_uint2(pack_bf2(h0, h1), pack_bf2(h2, h3));
    lo = make_uint2(pack_bf2(l0, l1), pack_bf2(l2, l3));
}

// mma.sync m16n8k16 bf16 -> f32 (portable, no 'a' features)
#define MMA_BF16(d, a, b0, b1) \
    asm volatile("mma.sync.aligned.m16n8k16.row.col.f32.bf16.bf16.f32 " \
        "{%0,%1,%2,%3}, {%4,%5,%6,%7}, {%8,%9}, {%0,%1,%2,%3};" \
        : "+f"((d)[0]), "+f"((d)[1]), "+f"((d)[2]), "+f"((d)[3]) \
        : "r"((a)[0]), "r"((a)[1]), "r"((a)[2]), "r"((a)[3]), "r"(b0), "r"(b1))

// smem layout: bf16 tiles, row stride 272 bytes (128 bf16 + 16B pad -> conflict-free)
#define STRIDE    272
#define OFF_A_HI  0
#define OFF_A_LO  34816
#define OFF_BA_HI 69632
#define OFF_BA_LO 104448
#define OFF_BC_HI 139264
#define OFF_BC_LO 174080
#define SMEM_DYN  208896

// ---------------- packed fp32x2 helpers (xproj) ------------------------------
__device__ __forceinline__ void ffma2(ull& c, ull a, ull b) {
    asm("fma.rn.f32x2 %0, %1, %2, %3;" : "=l"(c) : "l"(a), "l"(b), "l"(c));
}
__device__ __forceinline__ ull pack2(float x, float y) {
    ull r; asm("mov.b64 %0, {%1, %2};" : "=l"(r) : "f"(x), "f"(y)); return r;
}
__device__ __forceinline__ float2 unpack2(ull v) {
    float2 r; asm("mov.b64 {%0, %1}, %2;" : "=f"(r.x), "=f"(r.y) : "l"(v)); return r;
}

// ---------------- x-projection GEMM (FFMA2 fp32, unchanged) ------------------
__global__ __launch_bounds__(256) void k_xproj(
    const float* __restrict__ value,
    const float* __restrict__ wxz, const float* __restrict__ wxr,
    const float* __restrict__ wxh,
    const float* __restrict__ bbz, const float* __restrict__ bbr,
    const float* __restrict__ bbh)
{
    __shared__ float As[8][132];
    __shared__ float Bs[8][128];
    const int n0 = blockIdx.x * 128;
    const int m0 = blockIdx.y * 128;
    const int gate = n0 >> 10;
    const int j0 = n0 & (NH - 1);
    const float* W    = (gate == 0) ? wxz : (gate == 1 ? wxr : wxh);
    const float* bias = (gate == 0) ? bbz : (gate == 1 ? bbr : bbh);
    const int b  = m0 >> 9;
    const int t0 = m0 & (NT - 1);
    const int tid = threadIdx.x;
    const int tx = tid & 15, ty = tid >> 4;

    ull acc[8][4];
#pragma unroll
    for (int r = 0; r < 8; r++)
#pragma unroll
        for (int c = 0; c < 4; c++) acc[r][c] = 0ull;

    const float* Abase = value + (size_t)b * ND * NT + t0;

    for (int kc = 0; kc < ND; kc += 8) {
#pragma unroll
        for (int i = 0; i < 4; i++) {
            int idx = i * 256 + tid; int mm = idx & 127; int kk = idx >> 7;
            As[kk][mm] = Abase[(size_t)(kc + kk) * NT + mm];
        }
#pragma unroll
        for (int i = 0; i < 4; i++) {
            int idx = i * 256 + tid; int nn = idx & 127; int kk = idx >> 7;
            Bs[kk][nn] = W[(size_t)(kc + kk) * NH + j0 + nn];
        }
        __syncthreads();
#pragma unroll
        for (int k = 0; k < 8; k++) {
            float4 a0 = *(const float4*)&As[k][ty * 8];
            float4 a1 = *(const float4*)&As[k][ty * 8 + 4];
            ull b0 = *(const ull*)&Bs[k][tx * 8];
            ull b1 = *(const ull*)&Bs[k][tx * 8 + 2];
            ull b2 = *(const ull*)&Bs[k][tx * 8 + 4];
            ull b3 = *(const ull*)&Bs[k][tx * 8 + 6];
            float av[8] = {a0.x, a0.y, a0.z, a0.w, a1.x, a1.y, a1.z, a1.w};
#pragma unroll
            for (int r = 0; r < 8; r++) {
                ull aa = pack2(av[r], av[r]);
                ffma2(acc[r][0], aa, b0);
                ffma2(acc[r][1], aa, b1);
                ffma2(acc[r][2], aa, b2);
                ffma2(acc[r][3], aa, b3);
            }
        }
        __syncthreads();
    }
#pragma unroll
    for (int r = 0; r < 8; r++) {
        int m = m0 + ty * 8 + r;
        float* dst = g_P + (size_t)m * NH3 + n0 + tx * 8;
        const float* bp = bias + j0 + tx * 8;
        float o[8];
#pragma unroll
        for (int c = 0; c < 4; c++) {
            float2 v = unpack2(acc[r][c]);
            o[2 * c]     = v.x + bp[2 * c];
            o[2 * c + 1] = v.y + bp[2 * c + 1];
        }
        *(float4*)dst       = make_float4(o[0], o[1], o[2], o[3]);
        *(float4*)(dst + 4) = make_float4(o[4], o[5], o[6], o[7]);
    }
}

// ---------------- persistent recurrence kernel (HMMA bf16 2-split) -----------
__global__ __launch_bounds__(NTHR, 1) void k_persist(
    const float* __restrict__ delta,
    const float* __restrict__ wdg, const float* __restrict__ bdg,
    const float* __restrict__ whz, const float* __restrict__ whr,
    const float* __restrict__ whh,
    float* __restrict__ out, float* __restrict__ hlast)
{
    extern __shared__ char smem[];
    const int bid = blockIdx.x;
    const int tid = threadIdx.x;
    const int wid = tid >> 5;
    const int lid = tid & 31;
    const int lane4 = lid >> 2;         // 0..7
    const int lq    = lid & 3;          // 0..3
    const int mbase = (wid & 3) * 32;   // warp m-strip (4 strips of 32)
    const int nbase = (wid >> 2) * 64;  // warp n-strip (2 strips of 64)

    // block roles
    const int n0A    = (bid >> 3) * 128;   // zr GEMM N base (0..2047)
    const int ksA    = bid & 7;
    const int kbaseA = ksA * 128;
    const int gate   = n0A >> 10;
    const int j0     = n0A & (NH - 1);
    const int n0C    = (bid >> 4) * 128;   // h~ GEMM N base (0..1023)
    const int ksC    = bid & 15;
    const int kbaseC = ksC * 64;

    char* As_h = smem + OFF_A_HI;
    char* As_l = smem + OFF_A_LO;
    char* Ba_h = smem + OFF_BA_HI;
    char* Ba_l = smem + OFF_BA_LO;
    char* Bc_h = smem + OFF_BC_HI;
    char* Bc_l = smem + OFF_BC_LO;

    // ---- prologue: gamma, zero a, weight-stationary B tiles ----
    for (int it = 0; it < 4; it++) {
        int idx4 = bid * 1024 + it * 256 + tid;
        int i = idx4 * 4;
        int t = i >> 10, j = i & (NH - 1);
        float d = delta[t];
        float4 w = *(const float4*)(wdg + j);
        float4 bb = *(const float4*)(bdg + j);
        float4 g;
        g.x = expf(-fmaxf(0.f, w.x * d + bb.x));
        g.y = expf(-fmaxf(0.f, w.y * d + bb.y));
        g.z = expf(-fmaxf(0.f, w.z * d + bb.z));
        g.w = expf(-fmaxf(0.f, w.w * d + bb.w));
        *(float4*)(g_gamma + i) = g;
    }
    *(float4*)(g_a + bid * NH + tid * 4) = make_float4(0.f, 0.f, 0.f, 0.f);

    {
        const float* Wzr = gate ? whr : whz;
#pragma unroll 1
        for (int it = 0; it < 16; it++) {           // B_zr: [n=128][k=128]
            int e = (it * 256 + tid) * 4;
            int n = e >> 7, k = e & 127;
            const float* s = Wzr + (size_t)(kbaseA + k) * NH + j0 + n;
            uint2 hi, lo;
            split4(s[0], s[NH], s[2 * NH], s[3 * NH], hi, lo);
            int off = n * STRIDE + k * 2;
            *(uint2*)(Ba_h + off) = hi;
            *(uint2*)(Ba_l + off) = lo;
        }
#pragma unroll 1
        for (int it = 0; it < 8; it++) {            // B_h: [n=128][k=64]
            int e = (it * 256 + tid) * 4;
            int n = e >> 6, k = e & 63;
            const float* s = whh + (size_t)(kbaseC + k) * NH + n0C + n;
            uint2 hi, lo;
            split4(s[0], s[NH], s[2 * NH], s[3 * NH], hi, lo);
            int off = n * STRIDE + k * 2;
            *(uint2*)(Bc_h + off) = hi;
            *(uint2*)(Bc_l + off) = lo;
        }
    }
    gridbar();

    for (int t = 0; t < NT; t++) {
        // ---- Phase A: zr partial = a @ [Whz|Whr] (M128,N128,K128) ----
        {
#pragma unroll 4
            for (int it = 0; it < 16; it++) {       // A fill: [m=128][k=128]
                int e = (it * 256 + tid) * 4;
                int m = e >> 7, k = e & 127;
                float4 v = *(const float4*)(g_a + m * NH + kbaseA + k);
                uint2 hi, lo;
                split4(v.x, v.y, v.z, v.w, hi, lo);
                int off = m * STRIDE + k * 2;
                *(uint2*)(As_h + off) = hi;
                *(uint2*)(As_l + off) = lo;
            }
            __syncthreads();

            float acc[2][8][4];
#pragma unroll
            for (int mt = 0; mt < 2; mt++)
#pragma unroll
                for (int nt = 0; nt < 8; nt++)
#pragma unroll
                    for (int c = 0; c < 4; c++) acc[mt][nt][c] = 0.f;

#pragma unroll 1
            for (int kk = 0; kk < 128; kk += 16) {
                uint32_t a_h[2][4], a_l[2][4];
#pragma unroll
                for (int mt = 0; mt < 2; mt++) {
                    int base = (mbase + mt * 16 + lane4) * STRIDE + kk * 2 + lq * 4;
                    a_h[mt][0] = *(const uint32_t*)(As_h + base);
                    a_h[mt][1] = *(const uint32_t*)(As_h + base + 8 * STRIDE);
                    a_h[mt][2] = *(const uint32_t*)(As_h + base + 16);
                    a_h[mt][3] = *(const uint32_t*)(As_h + base + 8 * STRIDE + 16);
                    a_l[mt][0] = *(const uint32_t*)(As_l + base);
                    a_l[mt][1] = *(const uint32_t*)(As_l + base + 8 * STRIDE);
                    a_l[mt][2] = *(const uint32_t*)(As_l + base + 16);
                    a_l[mt][3] = *(const uint32_t*)(As_l + base + 8 * STRIDE + 16);
                }
#pragma unroll
                for (int nt = 0; nt < 8; nt++) {
                    int bb = (nbase + nt * 8 + lane4) * STRIDE + kk * 2 + lq * 4;
                    uint32_t bh0 = *(const uint32_t*)(Ba_h + bb);
                    uint32_t bh1 = *(const uint32_t*)(Ba_h + bb + 16);
                    uint32_t bl0 = *(const uint32_t*)(Ba_l + bb);
                    uint32_t bl1 = *(const uint32_t*)(Ba_l + bb + 16);
#pragma unroll
                    for (int mt = 0; mt < 2; mt++) {
                        MMA_BF16(acc[mt][nt], a_h[mt], bh0, bh1);
                        MMA_BF16(acc[mt][nt], a_h[mt], bl0, bl1);
                        MMA_BF16(acc[mt][nt], a_l[mt], bh0, bh1);
                    }
                }
            }
            float* dst = g_zrpart[ksA];
#pragma unroll
            for (int mt = 0; mt < 2; mt++) {
                int m = mbase + mt * 16 + lane4;
#pragma unroll
                for (int nt = 0; nt < 8; nt++) {
                    int n = n0A + nbase + nt * 8 + lq * 2;
                    *(float2*)&dst[m * (2 * NH) + n] =
                        make_float2(acc[mt][nt][0], acc[mt][nt][1]);
                    *(float2*)&dst[(m + 8) * (2 * NH) + n] =
                        make_float2(acc[mt][nt][2], acc[mt][nt][3]);
                }
            }
        }
        gridbar();

        // ---- Phase B: z, r gates (block handles batch row b = bid) ----
        {
            const int b = bid;
            const float4* Pp = (const float4*)(g_P + ((size_t)(b * NT + t)) * NH3);
            float4 sz = Pp[tid];
            float4 sr = Pp[256 + tid];
#pragma unroll
            for (int ks = 0; ks < 8; ks++) {
                const float4* zp = (const float4*)(g_zrpart[ks] + b * 2 * NH);
                float4 v = zp[tid];
                sz.x += v.x; sz.y += v.y; sz.z += v.z; sz.w += v.w;
                float4 w = zp[256 + tid];
                sr.x += w.x; sr.y += w.y; sr.z += w.z; sr.w += w.w;
            }
            *(float4*)(g_z + b * NH + tid * 4) =
                make_float4(sigmf(sz.x), sigmf(sz.y), sigmf(sz.z), sigmf(sz.w));
            *(float4*)(g_r + b * NH + tid * 4) =
                make_float4(sigmf(sr.x), sigmf(sr.y), sigmf(sr.z), sigmf(sr.w));
        }
        gridbar();

        // ---- Phase C: h~ partial = (r*a) @ Whh (M128,N128,K64) ----
        {
#pragma unroll 4
            for (int it = 0; it < 8; it++) {        // A fill: [m=128][k=64]
                int e = (it * 256 + tid) * 4;
                int m = e >> 6, k = e & 63;
                float4 a = *(const float4*)(g_a + m * NH + kbaseC + k);
                float4 r = *(const float4*)(g_r + m * NH + kbaseC + k);
                uint2 hi, lo;
                split4(r.x * a.x, r.y * a.y, r.z * a.z, r.w * a.w, hi, lo);
                int off = m * STRIDE + k * 2;
                *(uint2*)(As_h + off) = hi;
                *(uint2*)(As_l + off) = lo;
            }
            __syncthreads();

            float acc[2][8][4];
#pragma unroll
            for (int mt = 0; mt < 2; mt++)
#pragma unroll
                for (int nt = 0; nt < 8; nt++)
#pragma unroll
                    for (int c = 0; c < 4; c++) acc[mt][nt][c] = 0.f;

#pragma unroll 1
            for (int kk = 0; kk < 64; kk += 16) {
                uint32_t a_h[2][4], a_l[2][4];
#pragma unroll
                for (int mt = 0; mt < 2; mt++) {
                    int base = (mbase + mt * 16 + lane4) * STRIDE + kk * 2 + lq * 4;
                    a_h[mt][0] = *(const uint32_t*)(As_h + base);
                    a_h[mt][1] = *(const uint32_t*)(As_h + base + 8 * STRIDE);
                    a_h[mt][2] = *(const uint32_t*)(As_h + base + 16);
                    a_h[mt][3] = *(const uint32_t*)(As_h + base + 8 * STRIDE + 16);
                    a_l[mt][0] = *(const uint32_t*)(As_l + base);
                    a_l[mt][1] = *(const uint32_t*)(As_l + base + 8 * STRIDE);
                    a_l[mt][2] = *(const uint32_t*)(As_l + base + 16);
                    a_l[mt][3] = *(const uint32_t*)(As_l + base + 8 * STRIDE + 16);
                }
#pragma unroll
                for (int nt = 0; nt < 8; nt++) {
                    int bb = (nbase + nt * 8 + lane4) * STRIDE + kk * 2 + lq * 4;
                    uint32_t bh0 = *(const uint32_t*)(Bc_h + bb);
                    uint32_t bh1 = *(const uint32_t*)(Bc_h + bb + 16);
                    uint32_t bl0 = *(const uint32_t*)(Bc_l + bb);
                    uint32_t bl1 = *(const uint32_t*)(Bc_l + bb + 16);
#pragma unroll
                    for (int mt = 0; mt < 2; mt++) {
                        MMA_BF16(acc[mt][nt], a_h[mt], bh0, bh1);
                        MMA_BF16(acc[mt][nt], a_h[mt], bl0, bl1);
                        MMA_BF16(acc[mt][nt], a_l[mt], bh0, bh1);
                    }
                }
            }
            float* dst = g_hpart[ksC];
#pragma unroll
            for (int mt = 0; mt < 2; mt++) {
                int m = mbase + mt * 16 + lane4;
#pragma unroll
                for (int nt = 0; nt < 8; nt++) {
                    int n = n0C + nbase + nt * 8 + lq * 2;
                    *(float2*)&dst[m * NH + n] =
                        make_float2(acc[mt][nt][0], acc[mt][nt][1]);
                    *(float2*)&dst[(m + 8) * NH + n] =
                        make_float2(acc[mt][nt][2], acc[mt][nt][3]);
                }
            }
        }
        gridbar();

        // ---- Phase D: h update, output, next a ----
        {
            const int b = bid;
            const float4* Pp = (const float4*)(g_P + ((size_t)(b * NT + t)) * NH3);
            float4 sh = Pp[512 + tid];
#pragma unroll
            for (int ks = 0; ks < 16; ks++) {
                const float4* hp = (const float4*)(g_hpart[ks] + b * NH);
                float4 v = hp[tid];
                sh.x += v.x; sh.y += v.y; sh.z += v.z; sh.w += v.w;
            }
            float4 zz = *(const float4*)(g_z + b * NH + tid * 4);
            float4 aa = *(const float4*)(g_a + b * NH + tid * 4);
            float4 hn;
            hn.x = (1.f - zz.x) * aa.x + zz.x * tanhf(sh.x);
            hn.y = (1.f - zz.y) * aa.y + zz.y * tanhf(sh.y);
            hn.z = (1.f - zz.z) * aa.z + zz.z * tanhf(sh.z);
            hn.w = (1.f - zz.w) * aa.w + zz.w * tanhf(sh.w);
            *(float4*)(out + ((size_t)(b * NT + t)) * NH + tid * 4) = hn;
            if (t + 1 < NT) {
                float4 gn = *(const float4*)(g_gamma + (t + 1) * NH + tid * 4);
                *(float4*)(g_a + b * NH + tid * 4) =
                    make_float4(gn.x * hn.x, gn.y * hn.y, gn.z * hn.z, gn.w * hn.w);
            } else {
                *(float4*)(hlast + b * NH + tid * 4) = hn;
            }
        }
        gridbar();
    }
}

// ---------------- launch -----------------------------------------------------
extern "C" void kernel_launch(void* const* d_in, const int* in_sizes, int n_in,
                              void* d_out, int out_size) {
    const float* value = (const float*)d_in[0];
    const float* delta = (const float*)d_in[1];
    const float* wdg   = (const float*)d_in[2];
    const float* wxz   = (const float*)d_in[3];
    const float* whz   = (const float*)d_in[4];
    const float* wxr   = (const float*)d_in[5];
    const float* whr   = (const float*)d_in[6];
    const float* wxh   = (const float*)d_in[7];
    const float* whh   = (const float*)d_in[8];
    const float* bdg   = (const float*)d_in[9];
    const float* bz    = (const float*)d_in[10];
    const float* br    = (const float*)d_in[11];
    const float* bh    = (const float*)d_in[12];
    float* out = (float*)d_out;
    float* hlast = out + ((size_t)out_size - (size_t)NB * NH);

    cudaFuncSetAttribute(k_persist, cudaFuncAttributeMaxDynamicSharedMemorySize, SMEM_DYN);

    k_xproj<<<dim3(24, 512), 256>>>(value, wxz, wxr, wxh, bz, br, bh);
    k_persist<<<NBLK, NTHR, SMEM_DYN>>>(delta, wdg, bdg, whz, whr, whh, out, hlast);
}

// round 5
// speedup vs baseline: 2.0274x; 1.2173x over previous
#include <cuda_runtime.h>
#include <math.h>
#include <stdint.h>

typedef unsigned long long ull;

#define NB 128
#define ND 256
#define NH 1024
#define NT 512
#define NH3 3072
#define NBLK 128
#define NTHR 256

// ---------------- scratch (static device globals) ---------------------------
__device__ float g_P[(size_t)NT * NB * NH3];   // x-projections (+bias)
__device__ float g_gamma[NT * NH];
__device__ float g_a[NB * NH];                 // a = gamma_t * h_{t-1}
__device__ float g_z[NB * NH];
__device__ float g_r[NB * NH];
__device__ float g_zrpart[8][NB * 2 * NH];
__device__ float g_hpart[8][NB * NH];

// ---------------- grid barrier ----------------------------------------------
__device__ unsigned g_bar_count = 0;
__device__ volatile unsigned g_bar_gen = 0;

__device__ __forceinline__ void gridbar() {
    __syncthreads();
    if (threadIdx.x == 0) {
        unsigned gen = g_bar_gen;
        __threadfence();
        if (atomicAdd(&g_bar_count, 1) == NBLK - 1) {
            g_bar_count = 0;
            __threadfence();
            g_bar_gen = gen + 1;
        } else {
            while (g_bar_gen == gen) {}
            __threadfence();
        }
    }
    __syncthreads();
}

// ---------------- helpers ----------------------------------------------------
__device__ __forceinline__ float sigmf(float x) { return 1.f / (1.f + expf(-x)); }

__device__ __forceinline__ uint32_t cvt_tf32(float x) {
    uint32_t r; asm("cvt.rna.tf32.f32 %0, %1;" : "=r"(r) : "f"(x)); return r;
}

#define MMA_TF32(d, a, b0, b1) \
    asm volatile("mma.sync.aligned.m16n8k8.row.col.f32.tf32.tf32.f32 " \
        "{%0,%1,%2,%3}, {%4,%5,%6,%7}, {%8,%9}, {%0,%1,%2,%3};" \
        : "+f"((d)[0]), "+f"((d)[1]), "+f"((d)[2]), "+f"((d)[3]) \
        : "r"((a)[0]), "r"((a)[1]), "r"((a)[2]), "r"((a)[3]), "r"(b0), "r"(b1))

// persist smem layout (bytes)
#define STRA      132                     // A row stride in 4B words
#define OFF_AS    0                       // 128*132*4 = 67584
#define OFF_BAF   67584                   // 16*16*32*8 = 65536
#define OFF_BCF   133120                  // 16*8*32*8  = 32768
#define SMEM_DYN  165888

// ---------------- x-projection GEMM (tf32 MMA) --------------------------------
__global__ __launch_bounds__(256) void k_xproj(
    const float* __restrict__ value,
    const float* __restrict__ wxz, const float* __restrict__ wxr,
    const float* __restrict__ wxh,
    const float* __restrict__ bbz, const float* __restrict__ bbr,
    const float* __restrict__ bbh)
{
    __shared__ uint32_t As[32 * 132];     // [k][m], stride 132
    __shared__ uint32_t Bs[128 * 36];     // [n][k], stride 36
    const int n0 = blockIdx.x * 128;
    const int m0 = blockIdx.y * 128;
    const int gate = n0 >> 10;
    const int j0 = n0 & (NH - 1);
    const float* W    = (gate == 0) ? wxz : (gate == 1 ? wxr : wxh);
    const float* bias = (gate == 0) ? bbz : (gate == 1 ? bbr : bbh);
    const int b  = m0 >> 9;
    const int t0 = m0 & (NT - 1);
    const int tid = threadIdx.x;
    const int wid = tid >> 5, lid = tid & 31;
    const int gid = lid >> 2, tig = lid & 3;
    const int mbase = (wid & 3) * 32;
    const int nstrip = (wid >> 2) * 64;

    float acc[2][8][4];
#pragma unroll
    for (int mt = 0; mt < 2; mt++)
#pragma unroll
        for (int nt = 0; nt < 8; nt++)
#pragma unroll
            for (int c = 0; c < 4; c++) acc[mt][nt][c] = 0.f;

    const float* Abase = value + (size_t)b * ND * NT + t0;

    for (int kc = 0; kc < ND; kc += 32) {
#pragma unroll
        for (int it = 0; it < 16; it++) {
            int idx = it * 256 + tid;
            int m = idx & 127, k = idx >> 7;
            As[k * 132 + m] = cvt_tf32(Abase[(size_t)(kc + k) * NT + m]);
        }
#pragma unroll
        for (int it = 0; it < 16; it++) {
            int idx = it * 256 + tid;
            int n = idx & 127, k = idx >> 7;
            Bs[n * 36 + k] = cvt_tf32(W[(size_t)(kc + k) * NH + j0 + n]);
        }
        __syncthreads();
#pragma unroll
        for (int kk = 0; kk < 4; kk++) {
            int k0 = kk * 8;
            uint32_t a[2][4];
#pragma unroll
            for (int mt = 0; mt < 2; mt++) {
                int m = mbase + mt * 16 + gid;
                a[mt][0] = As[(k0 + tig) * 132 + m];
                a[mt][1] = As[(k0 + tig) * 132 + m + 8];
                a[mt][2] = As[(k0 + tig + 4) * 132 + m];
                a[mt][3] = As[(k0 + tig + 4) * 132 + m + 8];
            }
#pragma unroll
            for (int nt = 0; nt < 8; nt++) {
                int n = nstrip + nt * 8 + gid;
                uint32_t b0 = Bs[n * 36 + k0 + tig];
                uint32_t b1 = Bs[n * 36 + k0 + tig + 4];
                MMA_TF32(acc[0][nt], a[0], b0, b1);
                MMA_TF32(acc[1][nt], a[1], b0, b1);
            }
        }
        __syncthreads();
    }
#pragma unroll
    for (int mt = 0; mt < 2; mt++) {
        int m = m0 + mbase + mt * 16 + gid;
#pragma unroll
        for (int nt = 0; nt < 8; nt++) {
            int nl = nstrip + nt * 8 + tig * 2;
            float b0v = bias[j0 + nl], b1v = bias[j0 + nl + 1];
            float* dst = g_P + (size_t)m * NH3 + n0 + nl;
            *(float2*)dst = make_float2(acc[mt][nt][0] + b0v, acc[mt][nt][1] + b1v);
            float* dst2 = g_P + (size_t)(m + 8) * NH3 + n0 + nl;
            *(float2*)dst2 = make_float2(acc[mt][nt][2] + b0v, acc[mt][nt][3] + b1v);
        }
    }
}

// ---------------- persistent recurrence kernel (tf32 MMA) --------------------
__global__ __launch_bounds__(NTHR, 1) void k_persist(
    const float* __restrict__ delta,
    const float* __restrict__ wdg, const float* __restrict__ bdg,
    const float* __restrict__ whz, const float* __restrict__ whr,
    const float* __restrict__ whh,
    float* __restrict__ out, float* __restrict__ hlast)
{
    extern __shared__ char smem[];
    uint32_t* As    = (uint32_t*)(smem + OFF_AS);     // [m128][k128] stride 132
    ull*      BAf   = (ull*)(smem + OFF_BAF);         // frag order [kk16][ntile16][lid32]
    ull*      BCf   = (ull*)(smem + OFF_BCF);         // frag order [kk16][ntile8][lid32]

    const int bid = blockIdx.x;
    const int tid = threadIdx.x;
    const int wid = tid >> 5;
    const int lid = tid & 31;
    const int gid = lid >> 2, tig = lid & 3;
    const int mbase = (wid & 3) * 32;
    const int wn    = wid >> 2;             // 0..1

    // block roles
    const int n0A    = (bid >> 3) * 128;    // zr: N base (0..2047)
    const int ksA    = bid & 7;
    const int kbaseA = ksA * 128;
    const int gate   = n0A >> 10;
    const int j0     = n0A & (NH - 1);
    const int n0C    = (bid >> 3) * 64;     // h~: N base (0..1023)
    const int ksC    = bid & 7;
    const int kbaseC = ksC * 128;

    // ---- prologue: gamma, zero a ----
    for (int it = 0; it < 4; it++) {
        int idx4 = bid * 1024 + it * 256 + tid;
        int i = idx4 * 4;
        int t = i >> 10, j = i & (NH - 1);
        float d = delta[t];
        float4 w = *(const float4*)(wdg + j);
        float4 bb = *(const float4*)(bdg + j);
        float4 g;
        g.x = expf(-fmaxf(0.f, w.x * d + bb.x));
        g.y = expf(-fmaxf(0.f, w.y * d + bb.y));
        g.z = expf(-fmaxf(0.f, w.z * d + bb.z));
        g.w = expf(-fmaxf(0.f, w.w * d + bb.w));
        *(float4*)(g_gamma + i) = g;
    }
    *(float4*)(g_a + bid * NH + tid * 4) = make_float4(0.f, 0.f, 0.f, 0.f);

    // ---- prologue: stationary weights -> fragment-order smem (tf32) ----
    {
        const float* Wzr = gate ? whr : whz;
#pragma unroll 1
        for (int it = 0; it < 64; it++) {          // 128n x 128k
            int idx = it * 256 + tid;
            int n = idx & 127, k = idx >> 7;
            uint32_t bits = cvt_tf32(Wzr[(size_t)(kbaseA + k) * NH + j0 + n]);
            int kk = k >> 3, pos = k & 7, ntile = n >> 3, g = n & 7;
            int lane = g * 4 + (pos & 3), half = pos >> 2;
            *(uint32_t*)((char*)BAf + ((size_t)(kk * 16 + ntile) * 32 + lane) * 8 + half * 4) = bits;
        }
#pragma unroll 1
        for (int it = 0; it < 32; it++) {          // 64n x 128k
            int idx = it * 256 + tid;
            int n = idx & 63, k = idx >> 6;
            uint32_t bits = cvt_tf32(whh[(size_t)(kbaseC + k) * NH + n0C + n]);
            int kk = k >> 3, pos = k & 7, ntile = n >> 3, g = n & 7;
            int lane = g * 4 + (pos & 3), half = pos >> 2;
            *(uint32_t*)((char*)BCf + ((size_t)(kk * 8 + ntile) * 32 + lane) * 8 + half * 4) = bits;
        }
    }
    gridbar();

    for (int t = 0; t < NT; t++) {
        // ---- Phase A: zr partial = a @ [Whz|Whr]  (M128,N128,K128) ----
        {
#pragma unroll 4
            for (int it = 0; it < 16; it++) {      // A fill [m][k]
                int e = (it * 256 + tid) * 4;
                int m = e >> 7, k = e & 127;
                float4 v = *(const float4*)(g_a + m * NH + kbaseA + k);
                uint4 w;
                w.x = cvt_tf32(v.x); w.y = cvt_tf32(v.y);
                w.z = cvt_tf32(v.z); w.w = cvt_tf32(v.w);
                *(uint4*)(As + m * STRA + k) = w;
            }
            __syncthreads();

            float acc[2][8][4];
#pragma unroll
            for (int mt = 0; mt < 2; mt++)
#pragma unroll
                for (int nt = 0; nt < 8; nt++)
#pragma unroll
                    for (int c = 0; c < 4; c++) acc[mt][nt][c] = 0.f;

#pragma unroll 4
            for (int kk = 0; kk < 16; kk++) {
                int k0 = kk * 8;
                uint32_t a[2][4];
#pragma unroll
                for (int mt = 0; mt < 2; mt++) {
                    const uint32_t* ap = As + (mbase + mt * 16 + gid) * STRA + k0 + tig;
                    a[mt][0] = ap[0];
                    a[mt][1] = ap[8 * STRA];
                    a[mt][2] = ap[4];
                    a[mt][3] = ap[8 * STRA + 4];
                }
                const ull* bp = BAf + (size_t)(kk * 16 + wn * 8) * 32 + lid;
#pragma unroll
                for (int nt = 0; nt < 8; nt++) {
                    ull bb = bp[nt * 32];
                    uint32_t b0 = (uint32_t)bb, b1 = (uint32_t)(bb >> 32);
                    MMA_TF32(acc[0][nt], a[0], b0, b1);
                    MMA_TF32(acc[1][nt], a[1], b0, b1);
                }
            }
            float* dst = g_zrpart[ksA];
#pragma unroll
            for (int mt = 0; mt < 2; mt++) {
                int m = mbase + mt * 16 + gid;
#pragma unroll
                for (int nt = 0; nt < 8; nt++) {
                    int n = n0A + wn * 64 + nt * 8 + tig * 2;
                    *(float2*)&dst[m * (2 * NH) + n] =
                        make_float2(acc[mt][nt][0], acc[mt][nt][1]);
                    *(float2*)&dst[(m + 8) * (2 * NH) + n] =
                        make_float2(acc[mt][nt][2], acc[mt][nt][3]);
                }
            }
        }
        gridbar();

        // ---- Phase B: z, r gates ----
        {
            const int b = bid;
            const float4* Pp = (const float4*)(g_P + ((size_t)(b * NT + t)) * NH3);
            float4 sz = Pp[tid];
            float4 sr = Pp[256 + tid];
#pragma unroll
            for (int ks = 0; ks < 8; ks++) {
                const float4* zp = (const float4*)(g_zrpart[ks] + b * 2 * NH);
                float4 v = zp[tid];
                sz.x += v.x; sz.y += v.y; sz.z += v.z; sz.w += v.w;
                float4 w = zp[256 + tid];
                sr.x += w.x; sr.y += w.y; sr.z += w.z; sr.w += w.w;
            }
            *(float4*)(g_z + b * NH + tid * 4) =
                make_float4(sigmf(sz.x), sigmf(sz.y), sigmf(sz.z), sigmf(sz.w));
            *(float4*)(g_r + b * NH + tid * 4) =
                make_float4(sigmf(sr.x), sigmf(sr.y), sigmf(sr.z), sigmf(sr.w));
        }
        gridbar();

        // ---- Phase C: h~ partial = (r*a) @ Whh  (M128,N64,K128) ----
        {
#pragma unroll 4
            for (int it = 0; it < 16; it++) {
                int e = (it * 256 + tid) * 4;
                int m = e >> 7, k = e & 127;
                float4 a = *(const float4*)(g_a + m * NH + kbaseC + k);
                float4 r = *(const float4*)(g_r + m * NH + kbaseC + k);
                uint4 w;
                w.x = cvt_tf32(r.x * a.x); w.y = cvt_tf32(r.y * a.y);
                w.z = cvt_tf32(r.z * a.z); w.w = cvt_tf32(r.w * a.w);
                *(uint4*)(As + m * STRA + k) = w;
            }
            __syncthreads();

            float acc[2][4][4];
#pragma unroll
            for (int mt = 0; mt < 2; mt++)
#pragma unroll
                for (int nt = 0; nt < 4; nt++)
#pragma unroll
                    for (int c = 0; c < 4; c++) acc[mt][nt][c] = 0.f;

#pragma unroll 4
            for (int kk = 0; kk < 16; kk++) {
                int k0 = kk * 8;
                uint32_t a[2][4];
#pragma unroll
                for (int mt = 0; mt < 2; mt++) {
                    const uint32_t* ap = As + (mbase + mt * 16 + gid) * STRA + k0 + tig;
                    a[mt][0] = ap[0];
                    a[mt][1] = ap[8 * STRA];
                    a[mt][2] = ap[4];
                    a[mt][3] = ap[8 * STRA + 4];
                }
                const ull* bp = BCf + (size_t)(kk * 8 + wn * 4) * 32 + lid;
#pragma unroll
                for (int nt = 0; nt < 4; nt++) {
                    ull bb = bp[nt * 32];
                    uint32_t b0 = (uint32_t)bb, b1 = (uint32_t)(bb >> 32);
                    MMA_TF32(acc[0][nt], a[0], b0, b1);
                    MMA_TF32(acc[1][nt], a[1], b0, b1);
                }
            }
            float* dst = g_hpart[ksC];
#pragma unroll
            for (int mt = 0; mt < 2; mt++) {
                int m = mbase + mt * 16 + gid;
#pragma unroll
                for (int nt = 0; nt < 4; nt++) {
                    int n = n0C + wn * 32 + nt * 8 + tig * 2;
                    *(float2*)&dst[m * NH + n] =
                        make_float2(acc[mt][nt][0], acc[mt][nt][1]);
                    *(float2*)&dst[(m + 8) * NH + n] =
                        make_float2(acc[mt][nt][2], acc[mt][nt][3]);
                }
            }
        }
        gridbar();

        // ---- Phase D: h update, output, next a ----
        {
            const int b = bid;
            const float4* Pp = (const float4*)(g_P + ((size_t)(b * NT + t)) * NH3);
            float4 sh = Pp[512 + tid];
#pragma unroll
            for (int ks = 0; ks < 8; ks++) {
                const float4* hp = (const float4*)(g_hpart[ks] + b * NH);
                float4 v = hp[tid];
                sh.x += v.x; sh.y += v.y; sh.z += v.z; sh.w += v.w;
            }
            float4 zz = *(const float4*)(g_z + b * NH + tid * 4);
            float4 aa = *(const float4*)(g_a + b * NH + tid * 4);
            float4 hn;
            hn.x = (1.f - zz.x) * aa.x + zz.x * tanhf(sh.x);
            hn.y = (1.f - zz.y) * aa.y + zz.y * tanhf(sh.y);
            hn.z = (1.f - zz.z) * aa.z + zz.z * tanhf(sh.z);
            hn.w = (1.f - zz.w) * aa.w + zz.w * tanhf(sh.w);
            *(float4*)(out + ((size_t)(b * NT + t)) * NH + tid * 4) = hn;
            if (t + 1 < NT) {
                float4 gn = *(const float4*)(g_gamma + (t + 1) * NH + tid * 4);
                *(float4*)(g_a + b * NH + tid * 4) =
                    make_float4(gn.x * hn.x, gn.y * hn.y, gn.z * hn.z, gn.w * hn.w);
            } else {
                *(float4*)(hlast + b * NH + tid * 4) = hn;
            }
        }
        gridbar();
    }
}

// ---------------- launch -----------------------------------------------------
extern "C" void kernel_launch(void* const* d_in, const int* in_sizes, int n_in,
                              void* d_out, int out_size) {
    const float* value = (const float*)d_in[0];
    const float* delta = (const float*)d_in[1];
    const float* wdg   = (const float*)d_in[2];
    const float* wxz   = (const float*)d_in[3];
    const float* whz   = (const float*)d_in[4];
    const float* wxr   = (const float*)d_in[5];
    const float* whr   = (const float*)d_in[6];
    const float* wxh   = (const float*)d_in[7];
    const float* whh   = (const float*)d_in[8];
    const float* bdg   = (const float*)d_in[9];
    const float* bz    = (const float*)d_in[10];
    const float* br    = (const float*)d_in[11];
    const float* bh    = (const float*)d_in[12];
    float* out = (float*)d_out;
    float* hlast = out + ((size_t)out_size - (size_t)NB * NH);

    cudaFuncSetAttribute(k_persist, cudaFuncAttributeMaxDynamicSharedMemorySize, SMEM_DYN);

    k_xproj<<<dim3(24, 512), 256>>>(value, wxz, wxr, wxh, bz, br, bh);
    k_persist<<<NBLK, NTHR, SMEM_DYN>>>(delta, wdg, bdg, whz, whr, whh, out, hlast);
}

// round 6
// speedup vs baseline: 2.1275x; 1.0494x over previous
#include <cuda_runtime.h>
#include <math.h>
#include <stdint.h>

typedef unsigned long long ull;

#define NB 128
#define ND 256
#define NH 1024
#define NT 512
#define NH3 3072
#define NBLK 128
#define NTHR 256

// ---------------- scratch (static device globals) ---------------------------
__device__ float g_P[(size_t)NT * NB * NH3];   // x-projections (+bias)
__device__ float g_gamma[NT * NH];
__device__ float g_a[NB * NH];                 // a = gamma_t * h_{t-1}
__device__ float g_z[NB * NH];
__device__ float g_r[NB * NH];
__device__ float g_zrpart[8][NB * 2 * NH];
__device__ float g_hpart[8][NB * NH];

// ---------------- grid barriers ----------------------------------------------
__device__ unsigned g_bar_count = 0;
__device__ volatile unsigned g_bar_gen = 0;
__device__ unsigned g_flags[NBLK * 32];        // one 128B line per block

// slow single-counter barrier (used once per launch, after flag reset)
__device__ __forceinline__ void gridbar_atomic() {
    __syncthreads();
    if (threadIdx.x == 0) {
        unsigned gen = g_bar_gen;
        __threadfence();
        if (atomicAdd(&g_bar_count, 1) == NBLK - 1) {
            g_bar_count = 0;
            __threadfence();
            g_bar_gen = gen + 1;
        } else {
            while (g_bar_gen == gen) {}
            __threadfence();
        }
    }
    __syncthreads();
}

// fast distributed flag barrier (gen strictly increasing within a launch)
__device__ __forceinline__ void gridbar(unsigned gen) {
    __syncthreads();
    if (threadIdx.x == 0) {
        __threadfence();
        *(volatile unsigned*)&g_flags[blockIdx.x * 32] = gen;
    }
    if (threadIdx.x < NBLK) {
        while (*(volatile unsigned*)&g_flags[threadIdx.x * 32] < gen) {}
    }
    __threadfence();
    __syncthreads();
}

// ---------------- helpers ----------------------------------------------------
__device__ __forceinline__ float sigmf(float x) { return 1.f / (1.f + expf(-x)); }

__device__ __forceinline__ uint32_t cvt_tf32(float x) {
    uint32_t r; asm("cvt.rna.tf32.f32 %0, %1;" : "=r"(r) : "f"(x)); return r;
}

#define MMA_TF32(d, a, b0, b1) \
    asm volatile("mma.sync.aligned.m16n8k8.row.col.f32.tf32.tf32.f32 " \
        "{%0,%1,%2,%3}, {%4,%5,%6,%7}, {%8,%9}, {%0,%1,%2,%3};" \
        : "+f"((d)[0]), "+f"((d)[1]), "+f"((d)[2]), "+f"((d)[3]) \
        : "r"((a)[0]), "r"((a)[1]), "r"((a)[2]), "r"((a)[3]), "r"(b0), "r"(b1))

// persist smem layout (bytes)
#define STRA      132                     // A row stride in 4B words
#define OFF_AS    0                       // 128*132*4 = 67584
#define OFF_BAF   67584                   // 16*16*32*8 = 65536
#define OFF_BCF   133120                  // 16*8*32*8  = 32768
#define SMEM_DYN  165888

// ---------------- x-projection GEMM (tf32 MMA) --------------------------------
__global__ __launch_bounds__(256) void k_xproj(
    const float* __restrict__ value,
    const float* __restrict__ wxz, const float* __restrict__ wxr,
    const float* __restrict__ wxh,
    const float* __restrict__ bbz, const float* __restrict__ bbr,
    const float* __restrict__ bbh)
{
    __shared__ uint32_t As[32 * 132];     // [k][m], stride 132
    __shared__ uint32_t Bs[128 * 36];     // [n][k], stride 36
    const int n0 = blockIdx.x * 128;
    const int m0 = blockIdx.y * 128;
    const int gate = n0 >> 10;
    const int j0 = n0 & (NH - 1);
    const float* W    = (gate == 0) ? wxz : (gate == 1 ? wxr : wxh);
    const float* bias = (gate == 0) ? bbz : (gate == 1 ? bbr : bbh);
    const int b  = m0 >> 9;
    const int t0 = m0 & (NT - 1);
    const int tid = threadIdx.x;
    const int wid = tid >> 5, lid = tid & 31;
    const int gid = lid >> 2, tig = lid & 3;
    const int mbase = (wid & 3) * 32;
    const int nstrip = (wid >> 2) * 64;

    float acc[2][8][4];
#pragma unroll
    for (int mt = 0; mt < 2; mt++)
#pragma unroll
        for (int nt = 0; nt < 8; nt++)
#pragma unroll
            for (int c = 0; c < 4; c++) acc[mt][nt][c] = 0.f;

    const float* Abase = value + (size_t)b * ND * NT + t0;

    for (int kc = 0; kc < ND; kc += 32) {
#pragma unroll
        for (int it = 0; it < 16; it++) {
            int idx = it * 256 + tid;
            int m = idx & 127, k = idx >> 7;
            As[k * 132 + m] = cvt_tf32(Abase[(size_t)(kc + k) * NT + m]);
        }
#pragma unroll
        for (int it = 0; it < 16; it++) {
            int idx = it * 256 + tid;
            int n = idx & 127, k = idx >> 7;
            Bs[n * 36 + k] = cvt_tf32(W[(size_t)(kc + k) * NH + j0 + n]);
        }
        __syncthreads();
#pragma unroll
        for (int kk = 0; kk < 4; kk++) {
            int k0 = kk * 8;
            uint32_t a[2][4];
#pragma unroll
            for (int mt = 0; mt < 2; mt++) {
                int m = mbase + mt * 16 + gid;
                a[mt][0] = As[(k0 + tig) * 132 + m];
                a[mt][1] = As[(k0 + tig) * 132 + m + 8];
                a[mt][2] = As[(k0 + tig + 4) * 132 + m];
                a[mt][3] = As[(k0 + tig + 4) * 132 + m + 8];
            }
#pragma unroll
            for (int nt = 0; nt < 8; nt++) {
                int n = nstrip + nt * 8 + gid;
                uint32_t b0 = Bs[n * 36 + k0 + tig];
                uint32_t b1 = Bs[n * 36 + k0 + tig + 4];
                MMA_TF32(acc[0][nt], a[0], b0, b1);
                MMA_TF32(acc[1][nt], a[1], b0, b1);
            }
        }
        __syncthreads();
    }
#pragma unroll
    for (int mt = 0; mt < 2; mt++) {
        int m = m0 + mbase + mt * 16 + gid;
#pragma unroll
        for (int nt = 0; nt < 8; nt++) {
            int nl = nstrip + nt * 8 + tig * 2;
            float b0v = bias[j0 + nl], b1v = bias[j0 + nl + 1];
            float* dst = g_P + (size_t)m * NH3 + n0 + nl;
            *(float2*)dst = make_float2(acc[mt][nt][0] + b0v, acc[mt][nt][1] + b1v);
            float* dst2 = g_P + (size_t)(m + 8) * NH3 + n0 + nl;
            *(float2*)dst2 = make_float2(acc[mt][nt][2] + b0v, acc[mt][nt][3] + b1v);
        }
    }
}

// ---------------- persistent recurrence kernel (tf32 MMA) --------------------
__global__ __launch_bounds__(NTHR, 1) void k_persist(
    const float* __restrict__ delta,
    const float* __restrict__ wdg, const float* __restrict__ bdg,
    const float* __restrict__ whz, const float* __restrict__ whr,
    const float* __restrict__ whh,
    float* __restrict__ out, float* __restrict__ hlast)
{
    extern __shared__ char smem[];
    uint32_t* As    = (uint32_t*)(smem + OFF_AS);     // [m128][k128] stride 132
    ull*      BAf   = (ull*)(smem + OFF_BAF);         // frag order [kk16][ntile16][lid32]
    ull*      BCf   = (ull*)(smem + OFF_BCF);         // frag order [kk16][ntile8][lid32]

    const int bid = blockIdx.x;
    const int tid = threadIdx.x;
    const int wid = tid >> 5;
    const int lid = tid & 31;
    const int gid = lid >> 2, tig = lid & 3;
    const int mbase = (wid & 3) * 32;
    const int wn    = wid >> 2;             // 0..1

    // block roles
    const int n0A    = (bid >> 3) * 128;    // zr: N base (0..2047)
    const int ksA    = bid & 7;
    const int kbaseA = ksA * 128;
    const int gate   = n0A >> 10;
    const int j0     = n0A & (NH - 1);
    const int n0C    = (bid >> 3) * 64;     // h~: N base (0..1023)
    const int ksC    = bid & 7;
    const int kbaseC = ksC * 128;

    // ---- prologue: flag reset, gamma, zero a ----
    if (tid == 0) *(volatile unsigned*)&g_flags[bid * 32] = 0;

    for (int it = 0; it < 4; it++) {
        int idx4 = bid * 1024 + it * 256 + tid;
        int i = idx4 * 4;
        int t = i >> 10, j = i & (NH - 1);
        float d = delta[t];
        float4 w = *(const float4*)(wdg + j);
        float4 bb = *(const float4*)(bdg + j);
        float4 g;
        g.x = expf(-fmaxf(0.f, w.x * d + bb.x));
        g.y = expf(-fmaxf(0.f, w.y * d + bb.y));
        g.z = expf(-fmaxf(0.f, w.z * d + bb.z));
        g.w = expf(-fmaxf(0.f, w.w * d + bb.w));
        *(float4*)(g_gamma + i) = g;
    }
    *(float4*)(g_a + bid * NH + tid * 4) = make_float4(0.f, 0.f, 0.f, 0.f);

    // ---- prologue: stationary weights -> fragment-order smem (tf32) ----
    {
        const float* Wzr = gate ? whr : whz;
#pragma unroll 1
        for (int it = 0; it < 64; it++) {          // 128n x 128k
            int idx = it * 256 + tid;
            int n = idx & 127, k = idx >> 7;
            uint32_t bits = cvt_tf32(Wzr[(size_t)(kbaseA + k) * NH + j0 + n]);
            int kk = k >> 3, pos = k & 7, ntile = n >> 3, g = n & 7;
            int lane = g * 4 + (pos & 3), half = pos >> 2;
            *(uint32_t*)((char*)BAf + ((size_t)(kk * 16 + ntile) * 32 + lane) * 8 + half * 4) = bits;
        }
#pragma unroll 1
        for (int it = 0; it < 32; it++) {          // 64n x 128k
            int idx = it * 256 + tid;
            int n = idx & 63, k = idx >> 6;
            uint32_t bits = cvt_tf32(whh[(size_t)(kbaseC + k) * NH + n0C + n]);
            int kk = k >> 3, pos = k & 7, ntile = n >> 3, g = n & 7;
            int lane = g * 4 + (pos & 3), half = pos >> 2;
            *(uint32_t*)((char*)BCf + ((size_t)(kk * 8 + ntile) * 32 + lane) * 8 + half * 4) = bits;
        }
    }
    gridbar_atomic();      // publishes flag reset + gamma + a + weights
    unsigned gen = 0;

    for (int t = 0; t < NT; t++) {
        // ---- Phase A: zr partial = a @ [Whz|Whr]  (M128,N128,K128) ----
        {
#pragma unroll 4
            for (int it = 0; it < 16; it++) {      // A fill [m][k]
                int e = (it * 256 + tid) * 4;
                int m = e >> 7, k = e & 127;
                float4 v = *(const float4*)(g_a + m * NH + kbaseA + k);
                uint4 w;
                w.x = cvt_tf32(v.x); w.y = cvt_tf32(v.y);
                w.z = cvt_tf32(v.z); w.w = cvt_tf32(v.w);
                *(uint4*)(As + m * STRA + k) = w;
            }
            __syncthreads();

            float acc[2][8][4];
#pragma unroll
            for (int mt = 0; mt < 2; mt++)
#pragma unroll
                for (int nt = 0; nt < 8; nt++)
#pragma unroll
                    for (int c = 0; c < 4; c++) acc[mt][nt][c] = 0.f;

#pragma unroll 4
            for (int kk = 0; kk < 16; kk++) {
                int k0 = kk * 8;
                uint32_t a[2][4];
#pragma unroll
                for (int mt = 0; mt < 2; mt++) {
                    const uint32_t* ap = As + (mbase + mt * 16 + gid) * STRA + k0 + tig;
                    a[mt][0] = ap[0];
                    a[mt][1] = ap[8 * STRA];
                    a[mt][2] = ap[4];
                    a[mt][3] = ap[8 * STRA + 4];
                }
                const ull* bp = BAf + (size_t)(kk * 16 + wn * 8) * 32 + lid;
#pragma unroll
                for (int nt = 0; nt < 8; nt++) {
                    ull bb = bp[nt * 32];
                    uint32_t b0 = (uint32_t)bb, b1 = (uint32_t)(bb >> 32);
                    MMA_TF32(acc[0][nt], a[0], b0, b1);
                    MMA_TF32(acc[1][nt], a[1], b0, b1);
                }
            }
            float* dst = g_zrpart[ksA];
#pragma unroll
            for (int mt = 0; mt < 2; mt++) {
                int m = mbase + mt * 16 + gid;
#pragma unroll
                for (int nt = 0; nt < 8; nt++) {
                    int n = n0A + wn * 64 + nt * 8 + tig * 2;
                    *(float2*)&dst[m * (2 * NH) + n] =
                        make_float2(acc[mt][nt][0], acc[mt][nt][1]);
                    *(float2*)&dst[(m + 8) * (2 * NH) + n] =
                        make_float2(acc[mt][nt][2], acc[mt][nt][3]);
                }
            }
        }
        gridbar(++gen);

        // ---- Phase B: z, r gates ----
        {
            const int b = bid;
            const float4* Pp = (const float4*)(g_P + ((size_t)(b * NT + t)) * NH3);
            float4 sz = Pp[tid];
            float4 sr = Pp[256 + tid];
#pragma unroll
            for (int ks = 0; ks < 8; ks++) {
                const float4* zp = (const float4*)(g_zrpart[ks] + b * 2 * NH);
                float4 v = zp[tid];
                sz.x += v.x; sz.y += v.y; sz.z += v.z; sz.w += v.w;
                float4 w = zp[256 + tid];
                sr.x += w.x; sr.y += w.y; sr.z += w.z; sr.w += w.w;
            }
            *(float4*)(g_z + b * NH + tid * 4) =
                make_float4(sigmf(sz.x), sigmf(sz.y), sigmf(sz.z), sigmf(sz.w));
            *(float4*)(g_r + b * NH + tid * 4) =
                make_float4(sigmf(sr.x), sigmf(sr.y), sigmf(sr.z), sigmf(sr.w));
        }
        gridbar(++gen);

        // ---- Phase C: h~ partial = (r*a) @ Whh  (M128,N64,K128) ----
        {
#pragma unroll 4
            for (int it = 0; it < 16; it++) {
                int e = (it * 256 + tid) * 4;
                int m = e >> 7, k = e & 127;
                float4 a = *(const float4*)(g_a + m * NH + kbaseC + k);
                float4 r = *(const float4*)(g_r + m * NH + kbaseC + k);
                uint4 w;
                w.x = cvt_tf32(r.x * a.x); w.y = cvt_tf32(r.y * a.y);
                w.z = cvt_tf32(r.z * a.z); w.w = cvt_tf32(r.w * a.w);
                *(uint4*)(As + m * STRA + k) = w;
            }
            __syncthreads();

            float acc[2][4][4];
#pragma unroll
            for (int mt = 0; mt < 2; mt++)
#pragma unroll
                for (int nt = 0; nt < 4; nt++)
#pragma unroll
                    for (int c = 0; c < 4; c++) acc[mt][nt][c] = 0.f;

#pragma unroll 4
            for (int kk = 0; kk < 16; kk++) {
                int k0 = kk * 8;
                uint32_t a[2][4];
#pragma unroll
                for (int mt = 0; mt < 2; mt++) {
                    const uint32_t* ap = As + (mbase + mt * 16 + gid) * STRA + k0 + tig;
                    a[mt][0] = ap[0];
                    a[mt][1] = ap[8 * STRA];
                    a[mt][2] = ap[4];
                    a[mt][3] = ap[8 * STRA + 4];
                }
                const ull* bp = BCf + (size_t)(kk * 8 + wn * 4) * 32 + lid;
#pragma unroll
                for (int nt = 0; nt < 4; nt++) {
                    ull bb = bp[nt * 32];
                    uint32_t b0 = (uint32_t)bb, b1 = (uint32_t)(bb >> 32);
                    MMA_TF32(acc[0][nt], a[0], b0, b1);
                    MMA_TF32(acc[1][nt], a[1], b0, b1);
                }
            }
            float* dst = g_hpart[ksC];
#pragma unroll
            for (int mt = 0; mt < 2; mt++) {
                int m = mbase + mt * 16 + gid;
#pragma unroll
                for (int nt = 0; nt < 4; nt++) {
                    int n = n0C + wn * 32 + nt * 8 + tig * 2;
                    *(float2*)&dst[m * NH + n] =
                        make_float2(acc[mt][nt][0], acc[mt][nt][1]);
                    *(float2*)&dst[(m + 8) * NH + n] =
                        make_float2(acc[mt][nt][2], acc[mt][nt][3]);
                }
            }
        }
        gridbar(++gen);

        // ---- Phase D: h update, output, next a ----
        {
            const int b = bid;
            const float4* Pp = (const float4*)(g_P + ((size_t)(b * NT + t)) * NH3);
            float4 sh = Pp[512 + tid];
#pragma unroll
            for (int ks = 0; ks < 8; ks++) {
                const float4* hp = (const float4*)(g_hpart[ks] + b * NH);
                float4 v = hp[tid];
                sh.x += v.x; sh.y += v.y; sh.z += v.z; sh.w += v.w;
            }
            float4 zz = *(const float4*)(g_z + b * NH + tid * 4);
            float4 aa = *(const float4*)(g_a + b * NH + tid * 4);
            float4 hn;
            hn.x = (1.f - zz.x) * aa.x + zz.x * tanhf(sh.x);
            hn.y = (1.f - zz.y) * aa.y + zz.y * tanhf(sh.y);
            hn.z = (1.f - zz.z) * aa.z + zz.z * tanhf(sh.z);
            hn.w = (1.f - zz.w) * aa.w + zz.w * tanhf(sh.w);
            *(float4*)(out + ((size_t)(b * NT + t)) * NH + tid * 4) = hn;
            if (t + 1 < NT) {
                float4 gn = *(const float4*)(g_gamma + (t + 1) * NH + tid * 4);
                *(float4*)(g_a + b * NH + tid * 4) =
                    make_float4(gn.x * hn.x, gn.y * hn.y, gn.z * hn.z, gn.w * hn.w);
            } else {
                *(float4*)(hlast + b * NH + tid * 4) = hn;
            }
        }
        gridbar(++gen);
    }
}

// ---------------- launch -----------------------------------------------------
extern "C" void kernel_launch(void* const* d_in, const int* in_sizes, int n_in,
                              void* d_out, int out_size) {
    const float* value = (const float*)d_in[0];
    const float* delta = (const float*)d_in[1];
    const float* wdg   = (const float*)d_in[2];
    const float* wxz   = (const float*)d_in[3];
    const float* whz   = (const float*)d_in[4];
    const float* wxr   = (const float*)d_in[5];
    const float* whr   = (const float*)d_in[6];
    const float* wxh   = (const float*)d_in[7];
    const float* whh   = (const float*)d_in[8];
    const float* bdg   = (const float*)d_in[9];
    const float* bz    = (const float*)d_in[10];
    const float* br    = (const float*)d_in[11];
    const float* bh    = (const float*)d_in[12];
    float* out = (float*)d_out;
    float* hlast = out + ((size_t)out_size - (size_t)NB * NH);

    cudaFuncSetAttribute(k_persist, cudaFuncAttributeMaxDynamicSharedMemorySize, SMEM_DYN);

    k_xproj<<<dim3(24, 512), 256>>>(value, wxz, wxr, wxh, bz, br, bh);
    k_persist<<<NBLK, NTHR, SMEM_DYN>>>(delta, wdg, bdg, whz, whr, whh, out, hlast);
}